// round 6
// baseline (speedup 1.0000x reference)
#include <cuda_runtime.h>
#include <math.h>
#include <stdint.h>

// ---------------------------------------------------------------------------
// BiLSTM: B=32, T=512, D=512, H=512.
//   K0: transpose x[b][t][d] -> g_xT[t] in pair layout (d>>2)*128 + b*4 + (d&3)
//   K1: xg precompute, 256 thr, f32x2 dot, cp.async double-buffered x tiles
//   K2: persistent recurrence, 128 blocks x 256 threads:
//       warps 0-3 = fwd engine (4 units), warps 4-7 = bwd engine (4 units),
//       independent named barriers + flags per direction; f32x2 dot.
// ---------------------------------------------------------------------------

#define BB 32
#define TT 512
#define DD 512
#define HH 512
#define G4 2048
#define NBLK 128

typedef unsigned long long ull;

__device__ float g_xT[(size_t)TT * DD * BB];      // [t][pair layout]
__device__ float g_xg[(size_t)2 * TT * G4 * BB];  // [dir][t][g][b]
// h pair layout per (buf,dir): float idx = (j>>2)*128 + lane*4 + (j&3)
__device__ float g_hp[2 * 2 * 16384];             // [buf][dir][16384]
__device__ int   g_flags[2 * NBLK];               // [dir][block]

__device__ __forceinline__ float sigmoidf_(float x) {
    return 1.0f / (1.0f + expf(-x));
}
__device__ __forceinline__ ull ffma2(ull a, ull b, ull c) {
    ull d;
    asm("fma.rn.f32x2 %0, %1, %2, %3;" : "=l"(d) : "l"(a), "l"(b), "l"(c));
    return d;
}
__device__ __forceinline__ float sum2(ull v) {
    float a, b;
    asm("mov.b64 {%0, %1}, %2;" : "=f"(a), "=f"(b) : "l"(v));
    return a + b;
}
__device__ __forceinline__ void ebar(int id) {   // engine barrier: 128 threads
    asm volatile("bar.sync %0, 128;" :: "r"(id) : "memory");
}
__device__ __forceinline__ void cpa16(uint32_t s, const void* g) {
    asm volatile("cp.async.cg.shared.global [%0], [%1], 16;" :: "r"(s), "l"(g));
}
__device__ __forceinline__ void cpa_commit() {
    asm volatile("cp.async.commit_group;");
}
template <int N> __device__ __forceinline__ void cpa_wait() {
    asm volatile("cp.async.wait_group %0;" :: "n"(N));
}

// ---------------------------------------------------------------------------
__global__ void init_kernel() {
    int i = blockIdx.x * blockDim.x + threadIdx.x;
    if (i < 2 * NBLK) g_flags[i] = 0;
    if (i < 2 * 2 * 16384) g_hp[i] = 0.f;
}

// ---------------------------------------------------------------------------
// K0: transpose x[b][t][d] -> pair layout per t
// ---------------------------------------------------------------------------
__global__ void transpose_x(const float* __restrict__ x) {
    int t = blockIdx.x;
    int d0 = blockIdx.y * 32;
    __shared__ float tile[32][33];
    int tid = threadIdx.x;
    {
        int b = tid >> 3;
        int dq = (tid & 7) * 4;
        float4 v = *(const float4*)(x + ((size_t)(b * TT + t)) * DD + d0 + dq);
        tile[b][dq + 0] = v.x; tile[b][dq + 1] = v.y;
        tile[b][dq + 2] = v.z; tile[b][dq + 3] = v.w;
    }
    __syncthreads();
    {
        int d = tid >> 3;                 // local d 0..31
        int bq = (tid & 7) * 4;
        int dg = d0 + d;
        float* base = g_xT + (size_t)t * DD * 32 + (dg >> 2) * 128 + (dg & 3);
        base[(size_t)(bq + 0) * 4] = tile[bq + 0][d];
        base[(size_t)(bq + 1) * 4] = tile[bq + 1][d];
        base[(size_t)(bq + 2) * 4] = tile[bq + 2][d];
        base[(size_t)(bq + 3) * 4] = tile[bq + 3][d];
    }
}

// ---------------------------------------------------------------------------
// K1: xg precompute, f32x2. grid (64 tchunks, 128 tiles), 256 threads.
// smem: sW 64KB + sX[2] 128KB = 192KB
// ---------------------------------------------------------------------------
__global__ void __launch_bounds__(256, 1)
xg_kernel(const float* __restrict__ Wihf, const float* __restrict__ Wihb,
          const float* __restrict__ bihf, const float* __restrict__ bhhf,
          const float* __restrict__ bihb, const float* __restrict__ bhhb) {
    extern __shared__ float smem[];
    float* sW = smem;                         // 32 x 512
    float* sX0 = smem + 16384;                // pair layout, 64KB
    float* sX1 = smem + 32768;

    int tc = blockIdx.x;
    int ry = blockIdx.y;
    int dir = ry >> 6;
    int gbase = (ry & 63) * 32;
    const float* Wih = dir ? Wihb : Wihf;
    const float* bih = dir ? bihb : bihf;
    const float* bhh = dir ? bhhb : bhhf;
    int tid = threadIdx.x, w = tid >> 5, lane = tid & 31;

    {   // W tile: 32 consecutive rows
        const float4* src = (const float4*)(Wih + (size_t)gbase * DD);
        float4* dst = (float4*)sW;
        for (int i = tid; i < 32 * 128; i += 256) dst[i] = src[i];
    }
    float bias[4];
#pragma unroll
    for (int q = 0; q < 4; q++) {
        int g = gbase + q * 8 + w;
        bias[q] = bih[g] + bhh[g];
    }
    const float* wr0 = sW + (size_t)(w     ) * 512;
    const float* wr1 = sW + (size_t)(w +  8) * 512;
    const float* wr2 = sW + (size_t)(w + 16) * 512;
    const float* wr3 = sW + (size_t)(w + 24) * 512;

    uint32_t sx0a = (uint32_t)__cvta_generic_to_shared(sX0);
    uint32_t sx1a = (uint32_t)__cvta_generic_to_shared(sX1);

    int t0 = tc * 8;
    {   // prologue: x tile for it=0
        const char* src = (const char*)(g_xT + (size_t)t0 * DD * 32);
#pragma unroll
        for (int i = 0; i < 16; i++)
            cpa16(sx0a + (tid + i * 256) * 16, src + (size_t)(tid + i * 256) * 16);
        cpa_commit();
    }
#pragma unroll 1
    for (int it = 0; it < 8; it++) {
        if (it < 7) {
            uint32_t dsta = ((it + 1) & 1) ? sx1a : sx0a;
            const char* src = (const char*)(g_xT + (size_t)(t0 + it + 1) * DD * 32);
#pragma unroll
            for (int i = 0; i < 16; i++)
                cpa16(dsta + (tid + i * 256) * 16, src + (size_t)(tid + i * 256) * 16);
            cpa_commit();
            cpa_wait<1>();
        } else {
            cpa_wait<0>();
        }
        __syncthreads();

        const ulonglong2* sX = (const ulonglong2*)((it & 1) ? sX1 : sX0);
        ull acc0 = 0, acc1 = 0, acc2 = 0, acc3 = 0;
#pragma unroll 4
        for (int k4 = 0; k4 < 128; k4++) {
            ulonglong2 hp = sX[(size_t)k4 * 32 + lane];
            ulonglong2 wa = *(const ulonglong2*)(wr0 + 4 * k4);
            ulonglong2 wb = *(const ulonglong2*)(wr1 + 4 * k4);
            ulonglong2 wc = *(const ulonglong2*)(wr2 + 4 * k4);
            ulonglong2 wd = *(const ulonglong2*)(wr3 + 4 * k4);
            acc0 = ffma2(wa.x, hp.x, acc0); acc0 = ffma2(wa.y, hp.y, acc0);
            acc1 = ffma2(wb.x, hp.x, acc1); acc1 = ffma2(wb.y, hp.y, acc1);
            acc2 = ffma2(wc.x, hp.x, acc2); acc2 = ffma2(wc.y, hp.y, acc2);
            acc3 = ffma2(wd.x, hp.x, acc3); acc3 = ffma2(wd.y, hp.y, acc3);
        }

        int t = t0 + it;
        float* outp = g_xg + (((size_t)dir * TT + t) * G4 + gbase) * 32;
        __stcs(outp + (size_t)(0 * 8 + w) * 32 + lane, sum2(acc0) + bias[0]);
        __stcs(outp + (size_t)(1 * 8 + w) * 32 + lane, sum2(acc1) + bias[1]);
        __stcs(outp + (size_t)(2 * 8 + w) * 32 + lane, sum2(acc2) + bias[2]);
        __stcs(outp + (size_t)(3 * 8 + w) * 32 + lane, sum2(acc3) + bias[3]);
        __syncthreads();
    }
}

// ---------------------------------------------------------------------------
// K2: persistent recurrence, dual-engine.
// 128 blocks x 256 threads. dir = tid>>7 (warps 0-3 fwd, 4-7 bwd).
// Engine owns 4 units (jbase = blk*4): warp w = unit jbase+w, lane = batch.
// Rows in sW: r = gate*4 + unit. Independent barriers (id 1+dir) and flags.
// smem: sW 2x32KB + sH 2x64KB = 192KB
// ---------------------------------------------------------------------------
__global__ void __launch_bounds__(256, 1)
rec_kernel(const float* __restrict__ Whhf, const float* __restrict__ Whhb,
           const int* __restrict__ lengths, float* __restrict__ out) {
    extern __shared__ float smem[];
    __shared__ float sOut[2][32][4];

    int tid = threadIdx.x;
    int dir = tid >> 7;
    int etid = tid & 127;
    int w = etid >> 5, lane = etid & 31;
    int blk = blockIdx.x;
    int jbase = blk * 4;
    const float* Whh = dir ? Whhb : Whhf;
    float* sWd = smem + dir * 8192;                 // 16 rows x 512
    ull*   sHd = (ull*)(smem + 16384 + dir * 16384);// 64KB pair buffer

    // W_hh slice: local row r = g*4+u  ->  global row g*512 + jbase + u
    for (int i = etid; i < 16 * 128; i += 128) {
        int r = i >> 7, c4 = i & 127;
        int g = r >> 2, u = r & 3;
        ((float4*)sWd)[i] = ((const float4*)Whh)[(size_t)(g * HH + jbase + u) * 128 + c4];
    }

    int mylen = lengths[lane];
    int j = jbase + w;
    float c = 0.f, h = 0.f;
    const float* xgd = g_xg + (size_t)dir * TT * G4 * 32;
    const int bid = 1 + dir;                        // named barrier id
    const float* wr0 = sWd + (size_t)(0 * 4 + w) * 512;
    const float* wr1 = sWd + (size_t)(1 * 4 + w) * 512;
    const float* wr2 = sWd + (size_t)(2 * 4 + w) * 512;
    const float* wr3 = sWd + (size_t)(3 * 4 + w) * 512;

    __syncthreads();   // W tiles ready (block-wide, once)

    for (int s = 0; s < TT; s++) {
        int t = dir ? (TT - 1 - s) : s;
        int buf = s & 1;

        // xg prefetch (DRAM stream; consumed at pointwise)
        const float* xgt = xgd + (size_t)t * G4 * 32;
        float xv0 = __ldcs(xgt + (size_t)(0 * HH + j) * 32 + lane);
        float xv1 = __ldcs(xgt + (size_t)(1 * HH + j) * 32 + lane);
        float xv2 = __ldcs(xgt + (size_t)(2 * HH + j) * 32 + lane);
        float xv3 = __ldcs(xgt + (size_t)(3 * HH + j) * 32 + lane);

        // stage h: 64KB from L2 into engine's sH (4096 ulonglong2 / 128 thr)
        {
            const ulonglong2* hsrc =
                (const ulonglong2*)(g_hp + (size_t)(buf * 2 + dir) * 16384);
            ulonglong2* sdst = (ulonglong2*)sHd;
#pragma unroll 8
            for (int i = etid; i < 4096; i += 128) sdst[i] = __ldcg(hsrc + i);
        }
        ebar(bid);

        // dot: 4 gate rows of unit j over K=512, f32x2
        ull acc0 = 0, acc1 = 0, acc2 = 0, acc3 = 0;
#pragma unroll 4
        for (int k4 = 0; k4 < 128; k4++) {
            ulonglong2 hp = *((const ulonglong2*)sHd + (size_t)k4 * 32 + lane);
            ulonglong2 wa = *(const ulonglong2*)(wr0 + 4 * k4);
            ulonglong2 wb = *(const ulonglong2*)(wr1 + 4 * k4);
            ulonglong2 wc = *(const ulonglong2*)(wr2 + 4 * k4);
            ulonglong2 wd = *(const ulonglong2*)(wr3 + 4 * k4);
            acc0 = ffma2(wa.x, hp.x, acc0); acc0 = ffma2(wa.y, hp.y, acc0);
            acc1 = ffma2(wb.x, hp.x, acc1); acc1 = ffma2(wb.y, hp.y, acc1);
            acc2 = ffma2(wc.x, hp.x, acc2); acc2 = ffma2(wc.y, hp.y, acc2);
            acc3 = ffma2(wd.x, hp.x, acc3); acc3 = ffma2(wd.y, hp.y, acc3);
        }

        // pointwise
        {
            float gi = sigmoidf_(sum2(acc0) + xv0);
            float gf = sigmoidf_(sum2(acc1) + xv1);
            float gg = tanhf   (sum2(acc2) + xv2);
            float go = sigmoidf_(sum2(acc3) + xv3);
            float cn = gf * c + gi * gg;
            float hn = go * tanhf(cn);
            if (t < mylen) { c = cn; h = hn; }
        }

        // publish h (pair layout: blk*128 + lane*4 + w) + stage output
        __stcg(g_hp + (size_t)((buf ^ 1) * 2 + dir) * 16384 + blk * 128 + lane * 4 + w, h);
        sOut[dir][lane][w] = h;
        ebar(bid);

        // single-thread fence + flag (release pattern)
        if (etid == 0) {
            __threadfence();
            ((volatile int*)g_flags)[dir * NBLK + blk] = s + 1;
        }
        // output store (overlaps the poll below)
        if (etid < 32) {
            float4 v;
            v.x = sOut[dir][etid][0]; v.y = sOut[dir][etid][1];
            v.z = sOut[dir][etid][2]; v.w = sOut[dir][etid][3];
            *(float4*)(out + ((size_t)(etid * TT + t)) * 1024 + dir * HH + jbase) = v;
        }
        // poll all producers of this direction
        {
            volatile int* f = (volatile int*)&g_flags[dir * NBLK + etid];
            while (*f < s + 1) { }
        }
        ebar(bid);
    }
}

// ---------------------------------------------------------------------------
extern "C" void kernel_launch(void* const* d_in, const int* in_sizes, int n_in,
                              void* d_out, int out_size) {
    const float* x      = (const float*)d_in[0];
    const int*   lens   = (const int*)  d_in[1];
    const float* W_ih_f = (const float*)d_in[2];
    const float* W_hh_f = (const float*)d_in[3];
    const float* b_ih_f = (const float*)d_in[4];
    const float* b_hh_f = (const float*)d_in[5];
    const float* W_ih_b = (const float*)d_in[6];
    const float* W_hh_b = (const float*)d_in[7];
    const float* b_ih_b = (const float*)d_in[8];
    const float* b_hh_b = (const float*)d_in[9];
    float* out = (float*)d_out;

    cudaFuncSetAttribute(xg_kernel,  cudaFuncAttributeMaxDynamicSharedMemorySize, 196608);
    cudaFuncSetAttribute(rec_kernel, cudaFuncAttributeMaxDynamicSharedMemorySize, 196608);

    init_kernel<<<256, 256>>>();
    transpose_x<<<dim3(TT, DD / 32), 256>>>(x);
    xg_kernel<<<dim3(64, 128), 256, 196608>>>(W_ih_f, W_ih_b, b_ih_f, b_hh_f, b_ih_b, b_hh_b);
    rec_kernel<<<NBLK, 256, 196608>>>(W_hh_f, W_hh_b, lens, out);
}

// round 8
// speedup vs baseline: 1.5266x; 1.5266x over previous
#include <cuda_runtime.h>
#include <cuda_bf16.h>
#include <math.h>
#include <stdint.h>

// ---------------------------------------------------------------------------
// BiLSTM: B=32, T=512, D=512, H=512.
//   prep_w / prep_x: bf16 split (hi + lo) of W_ih and x
//   xg_mma: HMMA (mma.sync bf16) 3-split GEMM -> g_xg[dir][t][g][b]
//   rec_kernel: persistent fp32 recurrence (R4 version, best measured)
// ---------------------------------------------------------------------------

#define BB 32
#define TT 512
#define DD 512
#define HH 512
#define G4 2048
#define NBLK 128

typedef unsigned long long ull;

__device__ float g_xg[(size_t)2 * TT * G4 * BB];  // [dir][t][g][b]
__device__ float g_hp[2 * 2 * 16384];             // [buf][dir][pair layout]
__device__ int   g_flags[NBLK];
__device__ __nv_bfloat16 g_Whi[(size_t)2 * G4 * DD];
__device__ __nv_bfloat16 g_Wlo[(size_t)2 * G4 * DD];
__device__ __nv_bfloat16 g_xhi[(size_t)BB * TT * DD];
__device__ __nv_bfloat16 g_xlo[(size_t)BB * TT * DD];

__device__ __forceinline__ float sigmoidf_(float x) {
    return 1.0f / (1.0f + expf(-x));
}
__device__ __forceinline__ ull ffma2(ull a, ull b, ull c) {
    ull d;
    asm("fma.rn.f32x2 %0, %1, %2, %3;" : "=l"(d) : "l"(a), "l"(b), "l"(c));
    return d;
}
__device__ __forceinline__ float sum2(ull v) {
    float a, b;
    asm("mov.b64 {%0, %1}, %2;" : "=f"(a), "=f"(b) : "l"(v));
    return a + b;
}
__device__ __forceinline__ void cpa16(uint32_t s, const void* g) {
    asm volatile("cp.async.cg.shared.global [%0], [%1], 16;" :: "r"(s), "l"(g));
}
__device__ __forceinline__ void cpa_commit() {
    asm volatile("cp.async.commit_group;");
}
template <int N> __device__ __forceinline__ void cpa_wait() {
    asm volatile("cp.async.wait_group %0;" :: "n"(N));
}
__device__ __forceinline__ uint32_t smem_u32(const void* p) {
    return (uint32_t)__cvta_generic_to_shared(p);
}
__device__ __forceinline__ void ldsm4(uint32_t* r, uint32_t a) {
    asm volatile("ldmatrix.sync.aligned.m8n8.x4.shared.b16 {%0,%1,%2,%3}, [%4];"
                 : "=r"(r[0]), "=r"(r[1]), "=r"(r[2]), "=r"(r[3]) : "r"(a));
}
__device__ __forceinline__ void mma16816(float* c, const uint32_t* a,
                                         const uint32_t* b) {
    asm volatile(
        "mma.sync.aligned.m16n8k16.row.col.f32.bf16.bf16.f32 "
        "{%0,%1,%2,%3}, {%4,%5,%6,%7}, {%8,%9}, {%0,%1,%2,%3};"
        : "+f"(c[0]), "+f"(c[1]), "+f"(c[2]), "+f"(c[3])
        : "r"(a[0]), "r"(a[1]), "r"(a[2]), "r"(a[3]), "r"(b[0]), "r"(b[1]));
}

// ---------------------------------------------------------------------------
__global__ void init_kernel() {
    int i = blockIdx.x * blockDim.x + threadIdx.x;
    if (i < NBLK) g_flags[i] = 0;
    if (i < 2 * 2 * 16384) g_hp[i] = 0.f;
}

// ---------------------------------------------------------------------------
// bf16 split preps
// ---------------------------------------------------------------------------
__global__ void prep_w(const float* __restrict__ Wf, const float* __restrict__ Wb) {
    size_t i = (size_t)blockIdx.x * 256 + threadIdx.x;
    const size_t half = (size_t)G4 * DD;
    if (i >= 2 * half) return;
    float w = (i < half) ? Wf[i] : Wb[i - half];
    __nv_bfloat16 hi = __float2bfloat16(w);
    g_Whi[i] = hi;
    g_Wlo[i] = __float2bfloat16(w - __bfloat162float(hi));
}
__global__ void prep_x(const float* __restrict__ x) {
    size_t i = (size_t)blockIdx.x * 256 + threadIdx.x;
    if (i >= (size_t)BB * TT * DD) return;
    float v = x[i];
    __nv_bfloat16 hi = __float2bfloat16(v);
    g_xhi[i] = hi;
    g_xlo[i] = __float2bfloat16(v - __bfloat162float(hi));
}

// ---------------------------------------------------------------------------
// xg_mma: block = 128 gates x 64 N (2 t x 32 b), K=512 in 8 chunks of 64,
// double-buffered cp.async. 8 warps: warp_m = wid>>1 (32 gates),
// warp_n = wid&1 (one timestep). 3-split bf16 HMMA, fp32 accum.
// smem per buffer: Ahi 18432 + Alo 18432 + Bhi 9216 + Blo 9216 = 55296; x2.
// Tiles padded: row stride 72 bf16 (144 B) -> ldmatrix conflict-free.
// ---------------------------------------------------------------------------
#define XG_BUF 55296
#define XG_AROWB 144

__device__ __forceinline__ void xg_issue(uint32_t bbase, int kc, int gbase,
                                         const __nv_bfloat16* __restrict__ Whi,
                                         const __nv_bfloat16* __restrict__ Wlo,
                                         int t0, int tid) {
    int k0 = kc * 64;
#pragma unroll
    for (int i = tid; i < 3072; i += 256) {
        if (i < 2048) {
            int split = i >> 10, idx = i & 1023;
            int row = idx >> 3, seg = idx & 7;
            const __nv_bfloat16* src =
                (split ? Wlo : Whi) + (size_t)(gbase + row) * DD + k0 + seg * 8;
            cpa16(bbase + split * 18432 + row * XG_AROWB + seg * 16, src);
        } else {
            int j = i - 2048;
            int split = j >> 9, idx = j & 511;
            int row = idx >> 3, seg = idx & 7;
            int t = t0 + (row >> 5), b = row & 31;
            const __nv_bfloat16* src =
                (split ? g_xlo : g_xhi) + ((size_t)b * TT + t) * DD + k0 + seg * 8;
            cpa16(bbase + 36864 + split * 9216 + row * XG_AROWB + seg * 16, src);
        }
    }
}

__global__ void __launch_bounds__(256, 1)
xg_mma(const float* __restrict__ bihf, const float* __restrict__ bhhf,
       const float* __restrict__ bihb, const float* __restrict__ bhhb) {
    extern __shared__ unsigned char dsm[];
    int tid = threadIdx.x, wid = tid >> 5, lane = tid & 31;
    int nt = blockIdx.x, mb = blockIdx.y;
    int dir = mb >> 4, gbase = (mb & 15) * 128;
    int t0 = nt * 2;
    int warp_m = wid >> 1, warp_n = wid & 1;
    const __nv_bfloat16* Whi = g_Whi + (size_t)dir * G4 * DD;
    const __nv_bfloat16* Wlo = g_Wlo + (size_t)dir * G4 * DD;
    const float* bih = dir ? bihb : bihf;
    const float* bhh = dir ? bhhb : bhhf;

    float c[2][4][4];
#pragma unroll
    for (int mi = 0; mi < 2; mi++)
#pragma unroll
        for (int j = 0; j < 4; j++)
#pragma unroll
            for (int q = 0; q < 4; q++) c[mi][j][q] = 0.f;

    uint32_t sbase = smem_u32(dsm);

    // per-thread ldmatrix row/col parts
    int quad = lane >> 3, qr = lane & 7;
    int aRow = warp_m * 32 + (quad & 1) * 8 + qr;
    int colA = (quad >> 1) * 8;
    int bRow0 = warp_n * 32 + (quad >> 1) * 8 + qr;         // nhalf 0
    int bRow1 = bRow0 + 16;                                 // nhalf 1
    int colB = (quad & 1) * 8;

    xg_issue(sbase, 0, gbase, Whi, Wlo, t0, tid);
    cpa_commit();

#pragma unroll 1
    for (int kc = 0; kc < 8; kc++) {
        if (kc < 7) {
            xg_issue(sbase + ((kc + 1) & 1) * XG_BUF, kc + 1, gbase, Whi, Wlo, t0, tid);
            cpa_commit();
            cpa_wait<1>();
        } else {
            cpa_wait<0>();
        }
        __syncthreads();

        uint32_t bb = sbase + (kc & 1) * XG_BUF;
        uint32_t aHi = bb + (uint32_t)(aRow * XG_AROWB + colA * 2);
        uint32_t aLo = aHi + 18432;
        uint32_t bHi0 = bb + 36864 + (uint32_t)(bRow0 * XG_AROWB + colB * 2);
        uint32_t bHi1 = bb + 36864 + (uint32_t)(bRow1 * XG_AROWB + colB * 2);
        uint32_t bLo0 = bHi0 + 9216;
        uint32_t bLo1 = bHi1 + 9216;

#pragma unroll
        for (int ks = 0; ks < 4; ks++) {
            uint32_t ah0[4], ah1[4], al0[4], al1[4];
            uint32_t bh0[4], bh1[4], bl0[4], bl1[4];
            ldsm4(ah0, aHi + ks * 32);
            ldsm4(ah1, aHi + 2304 + ks * 32);   // +16 rows
            ldsm4(al0, aLo + ks * 32);
            ldsm4(al1, aLo + 2304 + ks * 32);
            ldsm4(bh0, bHi0 + ks * 32);
            ldsm4(bh1, bHi1 + ks * 32);
            ldsm4(bl0, bLo0 + ks * 32);
            ldsm4(bl1, bLo1 + ks * 32);
#pragma unroll
            for (int j = 0; j < 4; j++) {
                const uint32_t* Bh = ((j < 2) ? bh0 : bh1) + (j & 1) * 2;
                const uint32_t* Bl = ((j < 2) ? bl0 : bl1) + (j & 1) * 2;
                mma16816(c[0][j], ah0, Bh);
                mma16816(c[0][j], ah0, Bl);
                mma16816(c[0][j], al0, Bh);
                mma16816(c[1][j], ah1, Bh);
                mma16816(c[1][j], ah1, Bl);
                mma16816(c[1][j], al1, Bh);
            }
        }
        __syncthreads();
    }

    // store: c[mi][j][q] -> g_xg[dir][t0+warp_n][gbase+warp_m*32+m][b]
    int t = t0 + warp_n;
    float* outp = g_xg + (((size_t)dir * TT + t) * G4 + gbase + warp_m * 32) * 32;
    int tig = lane & 3, grp = lane >> 2;
#pragma unroll
    for (int mi = 0; mi < 2; mi++) {
        int m0 = mi * 16 + grp;
        int gg = gbase + warp_m * 32 + m0;
        float bia0 = bih[gg] + bhh[gg];
        float bia1 = bih[gg + 8] + bhh[gg + 8];
#pragma unroll
        for (int j = 0; j < 4; j++) {
            int b = j * 8 + tig * 2;
            float2 v0 = make_float2(c[mi][j][0] + bia0, c[mi][j][1] + bia0);
            float2 v1 = make_float2(c[mi][j][2] + bia1, c[mi][j][3] + bia1);
            __stcs((float2*)(outp + (size_t)m0 * 32 + b), v0);
            __stcs((float2*)(outp + (size_t)(m0 + 8) * 32 + b), v1);
        }
    }
}

// ---------------------------------------------------------------------------
// rec_kernel: R4 version verbatim (best measured). 128 blocks x 256 threads.
// ---------------------------------------------------------------------------
__global__ void __launch_bounds__(256, 1)
rec_kernel(const float* __restrict__ Whhf, const float* __restrict__ Whhb,
           const int* __restrict__ lengths, float* __restrict__ out) {
    extern __shared__ float smem[];
    float* sW = smem;                        // 32 rows x 512
    ull*   sHu = (ull*)(smem + 16384);       // [k4][lane][2] pairs
    __shared__ float sOut[32][8];

    int blk = blockIdx.x;
    int dir = blk >> 6;
    int jbase = (blk & 63) * 8;
    int tid = threadIdx.x, w = tid >> 5, lane = tid & 31;
    const float* Whh = dir ? Whhb : Whhf;

    for (int i = tid; i < 32 * 128; i += 256) {
        int r = i >> 7, c4 = i & 127;
        int g = r >> 3, u = r & 7;
        ((float4*)sW)[i] = ((const float4*)Whh)[(size_t)(g * HH + jbase + u) * 128 + c4];
    }

    int mylen = lengths[lane];
    int j = jbase + w;
    float c = 0.f, h = 0.f;
    const float* xgd = g_xg + (size_t)dir * TT * G4 * 32;
    const int hoff = (j >> 2) * 128 + lane * 4 + (j & 3);
    const float* wr0 = sW + (size_t)(w     ) * 512;
    const float* wr1 = sW + (size_t)(w +  8) * 512;
    const float* wr2 = sW + (size_t)(w + 16) * 512;
    const float* wr3 = sW + (size_t)(w + 24) * 512;

    for (int s = 0; s < TT; s++) {
        int t = dir ? (TT - 1 - s) : s;
        int buf = s & 1;

        const float* xgt = xgd + (size_t)t * G4 * 32;
        float xv0 = __ldcs(xgt + (size_t)(0 * HH + j) * 32 + lane);
        float xv1 = __ldcs(xgt + (size_t)(1 * HH + j) * 32 + lane);
        float xv2 = __ldcs(xgt + (size_t)(2 * HH + j) * 32 + lane);
        float xv3 = __ldcs(xgt + (size_t)(3 * HH + j) * 32 + lane);

        const ulonglong2* hsrc =
            (const ulonglong2*)(g_hp + (size_t)(buf * 2 + dir) * 16384);

        ull acc0 = 0, acc1 = 0, acc2 = 0, acc3 = 0;

        ulonglong2 r0 = __ldcg(hsrc + tid + 0 * 256);
        ulonglong2 r1 = __ldcg(hsrc + tid + 1 * 256);
        ulonglong2 r2 = __ldcg(hsrc + tid + 2 * 256);
        ulonglong2 r3 = __ldcg(hsrc + tid + 3 * 256);

#pragma unroll
        for (int cch = 0; cch < 4; cch++) {
            ulonglong2* sdst = (ulonglong2*)sHu + cch * 1024;
            sdst[tid + 0 * 256] = r0;
            sdst[tid + 1 * 256] = r1;
            sdst[tid + 2 * 256] = r2;
            sdst[tid + 3 * 256] = r3;
            __syncthreads();
            if (cch < 3) {
                r0 = __ldcg(hsrc + (cch + 1) * 1024 + tid + 0 * 256);
                r1 = __ldcg(hsrc + (cch + 1) * 1024 + tid + 1 * 256);
                r2 = __ldcg(hsrc + (cch + 1) * 1024 + tid + 2 * 256);
                r3 = __ldcg(hsrc + (cch + 1) * 1024 + tid + 3 * 256);
            }
            int k4b = cch * 32;
#pragma unroll 4
            for (int k4 = k4b; k4 < k4b + 32; k4++) {
                ulonglong2 hp = *((const ulonglong2*)sHu + (size_t)k4 * 32 + lane);
                ulonglong2 wa = *(const ulonglong2*)(wr0 + 4 * k4);
                ulonglong2 wb = *(const ulonglong2*)(wr1 + 4 * k4);
                ulonglong2 wc = *(const ulonglong2*)(wr2 + 4 * k4);
                ulonglong2 wd = *(const ulonglong2*)(wr3 + 4 * k4);
                acc0 = ffma2(wa.x, hp.x, acc0); acc0 = ffma2(wa.y, hp.y, acc0);
                acc1 = ffma2(wb.x, hp.x, acc1); acc1 = ffma2(wb.y, hp.y, acc1);
                acc2 = ffma2(wc.x, hp.x, acc2); acc2 = ffma2(wc.y, hp.y, acc2);
                acc3 = ffma2(wd.x, hp.x, acc3); acc3 = ffma2(wd.y, hp.y, acc3);
            }
        }

        {
            float gi = sigmoidf_(sum2(acc0) + xv0);
            float gf = sigmoidf_(sum2(acc1) + xv1);
            float gg = tanhf   (sum2(acc2) + xv2);
            float go = sigmoidf_(sum2(acc3) + xv3);
            float cn = gf * c + gi * gg;
            float hn = go * tanhf(cn);
            if (t < mylen) { c = cn; h = hn; }
        }

        __stcg(g_hp + (size_t)((buf ^ 1) * 2 + dir) * 16384 + hoff, h);
        sOut[lane][w] = h;

        __threadfence();
        __syncthreads();
        if (tid == 0) ((volatile int*)g_flags)[blk] = s + 1;
        if (tid >= 64 && tid < 128) {
            int idx = tid - 64;
            int b = idx >> 1, half = idx & 1;
            float4 v;
            v.x = sOut[b][half * 4 + 0]; v.y = sOut[b][half * 4 + 1];
            v.z = sOut[b][half * 4 + 2]; v.w = sOut[b][half * 4 + 3];
            *(float4*)(out + ((size_t)(b * TT + t)) * 1024 + dir * HH + jbase + half * 4) = v;
        }
        if (tid < 64) {
            volatile int* f = (volatile int*)&g_flags[dir * 64 + tid];
            while (*f < s + 1) { }
        }
        __syncthreads();
    }
}

// ---------------------------------------------------------------------------
extern "C" void kernel_launch(void* const* d_in, const int* in_sizes, int n_in,
                              void* d_out, int out_size) {
    const float* x      = (const float*)d_in[0];
    const int*   lens   = (const int*)  d_in[1];
    const float* W_ih_f = (const float*)d_in[2];
    const float* W_hh_f = (const float*)d_in[3];
    const float* b_ih_f = (const float*)d_in[4];
    const float* b_hh_f = (const float*)d_in[5];
    const float* W_ih_b = (const float*)d_in[6];
    const float* W_hh_b = (const float*)d_in[7];
    const float* b_ih_b = (const float*)d_in[8];
    const float* b_hh_b = (const float*)d_in[9];
    float* out = (float*)d_out;

    cudaFuncSetAttribute(xg_mma,     cudaFuncAttributeMaxDynamicSharedMemorySize, 2 * XG_BUF);
    cudaFuncSetAttribute(rec_kernel, cudaFuncAttributeMaxDynamicSharedMemorySize, 131072);

    init_kernel<<<256, 256>>>();
    prep_w<<<(2 * G4 * DD + 255) / 256, 256>>>(W_ih_f, W_ih_b);
    prep_x<<<(BB * TT * DD + 255) / 256, 256>>>(x);
    xg_mma<<<dim3(256, 32), 256, 2 * XG_BUF>>>(b_ih_f, b_hh_f, b_ih_b, b_hh_b);
    rec_kernel<<<NBLK, 256, 131072>>>(W_hh_f, W_hh_b, lens, out);
}

// round 9
// speedup vs baseline: 2.5619x; 1.6782x over previous
#include <cuda_runtime.h>
#include <cuda_bf16.h>
#include <math.h>
#include <stdint.h>

// ---------------------------------------------------------------------------
// BiLSTM: B=32, T=512, D=512, H=512.
//   prep_w / prep_whh / prep_x: bf16 split (hi + lo)
//   xg_mma: HMMA bf16 3-split GEMM -> g_xg[dir][t][g][b]      (R8, passing)
//   rec_kernel: persistent recurrence, HMMA bf16 3-split per step,
//               W_hh fragments register-resident, K-split across 8 warps
// ---------------------------------------------------------------------------

#define BB 32
#define TT 512
#define DD 512
#define HH 512
#define G4 2048
#define NBLK 128

typedef unsigned long long ull;

__device__ float g_xg[(size_t)2 * TT * G4 * BB];  // [dir][t][g][b]
__device__ __nv_bfloat16 g_hb[2 * 2 * 2 * 32 * 512]; // [buf][dir][split][b][512]
__device__ int   g_flags[NBLK];
__device__ __nv_bfloat16 g_Whi[(size_t)2 * G4 * DD];
__device__ __nv_bfloat16 g_Wlo[(size_t)2 * G4 * DD];
__device__ __nv_bfloat16 g_Hhi[(size_t)2 * G4 * HH];
__device__ __nv_bfloat16 g_Hlo[(size_t)2 * G4 * HH];
__device__ __nv_bfloat16 g_xhi[(size_t)BB * TT * DD];
__device__ __nv_bfloat16 g_xlo[(size_t)BB * TT * DD];

__device__ __forceinline__ float sigmoidf_(float x) {
    return 1.0f / (1.0f + expf(-x));
}
__device__ __forceinline__ void cpa16(uint32_t s, const void* g) {
    asm volatile("cp.async.cg.shared.global [%0], [%1], 16;" :: "r"(s), "l"(g));
}
__device__ __forceinline__ void cpa_commit() {
    asm volatile("cp.async.commit_group;");
}
template <int N> __device__ __forceinline__ void cpa_wait() {
    asm volatile("cp.async.wait_group %0;" :: "n"(N));
}
__device__ __forceinline__ uint32_t smem_u32(const void* p) {
    return (uint32_t)__cvta_generic_to_shared(p);
}
__device__ __forceinline__ void ldsm4(uint32_t* r, uint32_t a) {
    asm volatile("ldmatrix.sync.aligned.m8n8.x4.shared.b16 {%0,%1,%2,%3}, [%4];"
                 : "=r"(r[0]), "=r"(r[1]), "=r"(r[2]), "=r"(r[3]) : "r"(a));
}
__device__ __forceinline__ void mma16816(float* c, const uint32_t* a,
                                         const uint32_t* b) {
    asm volatile(
        "mma.sync.aligned.m16n8k16.row.col.f32.bf16.bf16.f32 "
        "{%0,%1,%2,%3}, {%4,%5,%6,%7}, {%8,%9}, {%0,%1,%2,%3};"
        : "+f"(c[0]), "+f"(c[1]), "+f"(c[2]), "+f"(c[3])
        : "r"(a[0]), "r"(a[1]), "r"(a[2]), "r"(a[3]), "r"(b[0]), "r"(b[1]));
}

// ---------------------------------------------------------------------------
__global__ void init_kernel() {
    int i = blockIdx.x * blockDim.x + threadIdx.x;
    if (i < NBLK) g_flags[i] = 0;
    ((uint32_t*)g_hb)[i] = 0u;   // 65536 words exactly, grid 256x256
}

// ---------------------------------------------------------------------------
// bf16 split preps
// ---------------------------------------------------------------------------
__global__ void prep_w(const float* __restrict__ Wf, const float* __restrict__ Wb) {
    size_t i = (size_t)blockIdx.x * 256 + threadIdx.x;
    const size_t half = (size_t)G4 * DD;
    if (i >= 2 * half) return;
    float w = (i < half) ? Wf[i] : Wb[i - half];
    __nv_bfloat16 hi = __float2bfloat16(w);
    g_Whi[i] = hi;
    g_Wlo[i] = __float2bfloat16(w - __bfloat162float(hi));
}
__global__ void prep_whh(const float* __restrict__ Wf, const float* __restrict__ Wb) {
    size_t i = (size_t)blockIdx.x * 256 + threadIdx.x;
    const size_t half = (size_t)G4 * HH;
    if (i >= 2 * half) return;
    float w = (i < half) ? Wf[i] : Wb[i - half];
    __nv_bfloat16 hi = __float2bfloat16(w);
    g_Hhi[i] = hi;
    g_Hlo[i] = __float2bfloat16(w - __bfloat162float(hi));
}
__global__ void prep_x(const float* __restrict__ x) {
    size_t i = (size_t)blockIdx.x * 256 + threadIdx.x;
    if (i >= (size_t)BB * TT * DD) return;
    float v = x[i];
    __nv_bfloat16 hi = __float2bfloat16(v);
    g_xhi[i] = hi;
    g_xlo[i] = __float2bfloat16(v - __bfloat162float(hi));
}

// ---------------------------------------------------------------------------
// xg_mma (R8 version, passing): block = 128 gates x 64 N (2t x 32b), K=512.
// ---------------------------------------------------------------------------
#define XG_BUF 55296
#define XG_AROWB 144

__device__ __forceinline__ void xg_issue(uint32_t bbase, int kc, int gbase,
                                         const __nv_bfloat16* __restrict__ Whi,
                                         const __nv_bfloat16* __restrict__ Wlo,
                                         int t0, int tid) {
    int k0 = kc * 64;
#pragma unroll
    for (int i = tid; i < 3072; i += 256) {
        if (i < 2048) {
            int split = i >> 10, idx = i & 1023;
            int row = idx >> 3, seg = idx & 7;
            const __nv_bfloat16* src =
                (split ? Wlo : Whi) + (size_t)(gbase + row) * DD + k0 + seg * 8;
            cpa16(bbase + split * 18432 + row * XG_AROWB + seg * 16, src);
        } else {
            int j = i - 2048;
            int split = j >> 9, idx = j & 511;
            int row = idx >> 3, seg = idx & 7;
            int t = t0 + (row >> 5), b = row & 31;
            const __nv_bfloat16* src =
                (split ? g_xlo : g_xhi) + ((size_t)b * TT + t) * DD + k0 + seg * 8;
            cpa16(bbase + 36864 + split * 9216 + row * XG_AROWB + seg * 16, src);
        }
    }
}

__global__ void __launch_bounds__(256, 1)
xg_mma(const float* __restrict__ bihf, const float* __restrict__ bhhf,
       const float* __restrict__ bihb, const float* __restrict__ bhhb) {
    extern __shared__ unsigned char dsm[];
    int tid = threadIdx.x, wid = tid >> 5, lane = tid & 31;
    int nt = blockIdx.x, mb = blockIdx.y;
    int dir = mb >> 4, gbase = (mb & 15) * 128;
    int t0 = nt * 2;
    int warp_m = wid >> 1, warp_n = wid & 1;
    const __nv_bfloat16* Whi = g_Whi + (size_t)dir * G4 * DD;
    const __nv_bfloat16* Wlo = g_Wlo + (size_t)dir * G4 * DD;
    const float* bih = dir ? bihb : bihf;
    const float* bhh = dir ? bhhb : bhhf;

    float c[2][4][4];
#pragma unroll
    for (int mi = 0; mi < 2; mi++)
#pragma unroll
        for (int j = 0; j < 4; j++)
#pragma unroll
            for (int q = 0; q < 4; q++) c[mi][j][q] = 0.f;

    uint32_t sbase = smem_u32(dsm);
    int quad = lane >> 3, qr = lane & 7;
    int aRow = warp_m * 32 + (quad & 1) * 8 + qr;
    int colA = (quad >> 1) * 8;
    int bRow0 = warp_n * 32 + (quad >> 1) * 8 + qr;
    int bRow1 = bRow0 + 16;
    int colB = (quad & 1) * 8;

    xg_issue(sbase, 0, gbase, Whi, Wlo, t0, tid);
    cpa_commit();

#pragma unroll 1
    for (int kc = 0; kc < 8; kc++) {
        if (kc < 7) {
            xg_issue(sbase + ((kc + 1) & 1) * XG_BUF, kc + 1, gbase, Whi, Wlo, t0, tid);
            cpa_commit();
            cpa_wait<1>();
        } else {
            cpa_wait<0>();
        }
        __syncthreads();

        uint32_t bb = sbase + (kc & 1) * XG_BUF;
        uint32_t aHi = bb + (uint32_t)(aRow * XG_AROWB + colA * 2);
        uint32_t aLo = aHi + 18432;
        uint32_t bHi0 = bb + 36864 + (uint32_t)(bRow0 * XG_AROWB + colB * 2);
        uint32_t bHi1 = bb + 36864 + (uint32_t)(bRow1 * XG_AROWB + colB * 2);
        uint32_t bLo0 = bHi0 + 9216;
        uint32_t bLo1 = bHi1 + 9216;

#pragma unroll
        for (int ks = 0; ks < 4; ks++) {
            uint32_t ah0[4], ah1[4], al0[4], al1[4];
            uint32_t bh0[4], bh1[4], bl0[4], bl1[4];
            ldsm4(ah0, aHi + ks * 32);
            ldsm4(ah1, aHi + 2304 + ks * 32);
            ldsm4(al0, aLo + ks * 32);
            ldsm4(al1, aLo + 2304 + ks * 32);
            ldsm4(bh0, bHi0 + ks * 32);
            ldsm4(bh1, bHi1 + ks * 32);
            ldsm4(bl0, bLo0 + ks * 32);
            ldsm4(bl1, bLo1 + ks * 32);
#pragma unroll
            for (int j = 0; j < 4; j++) {
                const uint32_t* Bh = ((j < 2) ? bh0 : bh1) + (j & 1) * 2;
                const uint32_t* Bl = ((j < 2) ? bl0 : bl1) + (j & 1) * 2;
                mma16816(c[0][j], ah0, Bh);
                mma16816(c[0][j], ah0, Bl);
                mma16816(c[0][j], al0, Bh);
                mma16816(c[1][j], ah1, Bh);
                mma16816(c[1][j], ah1, Bl);
                mma16816(c[1][j], al1, Bh);
            }
        }
        __syncthreads();
    }

    int t = t0 + warp_n;
    float* outp = g_xg + (((size_t)dir * TT + t) * G4 + gbase + warp_m * 32) * 32;
    int tig = lane & 3, grp = lane >> 2;
#pragma unroll
    for (int mi = 0; mi < 2; mi++) {
        int m0 = mi * 16 + grp;
        int gg = gbase + warp_m * 32 + m0;
        float bia0 = bih[gg] + bhh[gg];
        float bia1 = bih[gg + 8] + bhh[gg + 8];
#pragma unroll
        for (int j = 0; j < 4; j++) {
            int b = j * 8 + tig * 2;
            float2 v0 = make_float2(c[mi][j][0] + bia0, c[mi][j][1] + bia0);
            float2 v1 = make_float2(c[mi][j][2] + bia1, c[mi][j][3] + bia1);
            __stcs((float2*)(outp + (size_t)m0 * 32 + b), v0);
            __stcs((float2*)(outp + (size_t)(m0 + 8) * 32 + b), v1);
        }
    }
}

// ---------------------------------------------------------------------------
// rec_kernel: 128 blocks x 256 threads. Block = (dir, 8 units = 32 gate rows
// r = g*8+u). Warp w = K-slice [64w, 64w+64); W_hh bf16 hi/lo fragments in
// registers for all steps. h exchanged via L2 as bf16 hi/lo [b][512].
// smem: h staging 2x33280 | C partials 8x32x40 f32 | sG 32x32 f32.
// ---------------------------------------------------------------------------
#define HSTR 1040
#define HREG 33280
#define SC_OFF 66560
#define SG_OFF (66560 + 40960)

__global__ void __launch_bounds__(256, 1)
rec_kernel(const int* __restrict__ lengths, float* __restrict__ out) {
    extern __shared__ unsigned char sm[];
    float* sC = (float*)(sm + SC_OFF);     // [8][32][40]
    float* sG = (float*)(sm + SG_OFF);     // [32][32]
    __shared__ __nv_bfloat16 sPub[2][32][8];
    __shared__ float sOut[32][8];

    int blk = blockIdx.x;
    int dir = blk >> 6;
    int jbase = (blk & 63) * 8;
    int tid = threadIdx.x, wid = tid >> 5, lane = tid & 31;
    int quad = lane >> 3, qr = lane & 7;
    uint32_t sbase = smem_u32(sm);

    // ---- prologue: stage W_hh rows (hi @0, lo @SC_OFF), load fragments ----
    {
        const __nv_bfloat16* Hhi = g_Hhi + (size_t)dir * G4 * HH;
        const __nv_bfloat16* Hlo = g_Hlo + (size_t)dir * G4 * HH;
        for (int i = tid; i < 2048; i += 256) {
            int row = i >> 6, ch = i & 63;
            int g = row >> 3, u = row & 7;
            size_t src = (size_t)(g * 512 + jbase + u) * HH + ch * 8;
            *(float4*)(sm + row * HSTR + ch * 16) = *(const float4*)(Hhi + src);
            *(float4*)(sm + SC_OFF + row * HSTR + ch * 16) = *(const float4*)(Hlo + src);
        }
    }
    __syncthreads();

    uint32_t ahi[2][4][4], alo[2][4][4];
#pragma unroll
    for (int mi = 0; mi < 2; mi++) {
#pragma unroll
        for (int kt = 0; kt < 4; kt++) {
            int aRow = mi * 16 + (quad & 1) * 8 + qr;
            int colA = wid * 64 + kt * 16 + (quad >> 1) * 8;
            ldsm4(ahi[mi][kt], sbase + (uint32_t)(aRow * HSTR + colA * 2));
            ldsm4(alo[mi][kt], sbase + SC_OFF + (uint32_t)(aRow * HSTR + colA * 2));
        }
    }
    __syncthreads();

    int mylen = lengths[lane];
    int j = jbase + wid;                    // pointwise identity: (unit, batch)
    float cc = 0.f, hh = 0.f;
    const float* xgd = g_xg + (size_t)dir * TT * G4 * 32;
    int bRow0 = (quad >> 1) * 8 + qr;
    int colB = (quad & 1) * 8;
    int grp = lane >> 2, tig = lane & 3;

    for (int s = 0; s < TT; s++) {
        int t = dir ? (TT - 1 - s) : s;
        int buf = s & 1;

        // xg prefetch for pointwise (thread (wid=unit, lane=batch))
        const float* xgt = xgd + (size_t)t * G4 * 32;
        float xv0 = __ldcs(xgt + (size_t)(0 * HH + j) * 32 + lane);
        float xv1 = __ldcs(xgt + (size_t)(1 * HH + j) * 32 + lane);
        float xv2 = __ldcs(xgt + (size_t)(2 * HH + j) * 32 + lane);
        float xv3 = __ldcs(xgt + (size_t)(3 * HH + j) * 32 + lane);

        // stage h hi/lo [b][512] -> smem (padded rows)
        {
            const __nv_bfloat16* hs = g_hb + (size_t)(buf * 2 + dir) * 2 * 16384;
#pragma unroll
            for (int i = tid; i < 4096; i += 256) {
                int split = i >> 11, idx = i & 2047;
                int row = idx >> 6, ch = idx & 63;
                cpa16(sbase + split * HREG + (uint32_t)(row * HSTR + ch * 16),
                      hs + (size_t)split * 16384 + row * 512 + ch * 8);
            }
            cpa_commit();
            cpa_wait<0>();
        }
        __syncthreads();

        // MMA: warp's K-slice, 3-split
        float cf[2][4][4];
#pragma unroll
        for (int mi = 0; mi < 2; mi++)
#pragma unroll
            for (int jj = 0; jj < 4; jj++)
#pragma unroll
                for (int q = 0; q < 4; q++) cf[mi][jj][q] = 0.f;

#pragma unroll
        for (int kt = 0; kt < 4; kt++) {
            uint32_t ba = sbase + (uint32_t)(bRow0 * HSTR
                          + (wid * 64 + kt * 16 + colB) * 2);
            uint32_t bh0[4], bh1[4], bl0[4], bl1[4];
            ldsm4(bh0, ba);
            ldsm4(bh1, ba + 16 * HSTR);
            ldsm4(bl0, ba + HREG);
            ldsm4(bl1, ba + HREG + 16 * HSTR);
#pragma unroll
            for (int jj = 0; jj < 4; jj++) {
                const uint32_t* Bh = ((jj < 2) ? bh0 : bh1) + (jj & 1) * 2;
                const uint32_t* Bl = ((jj < 2) ? bl0 : bl1) + (jj & 1) * 2;
                mma16816(cf[0][jj], ahi[0][kt], Bh);
                mma16816(cf[0][jj], ahi[0][kt], Bl);
                mma16816(cf[0][jj], alo[0][kt], Bh);
                mma16816(cf[1][jj], ahi[1][kt], Bh);
                mma16816(cf[1][jj], ahi[1][kt], Bl);
                mma16816(cf[1][jj], alo[1][kt], Bh);
            }
        }

        // store partials sC[w][m][40]
        {
            float* cw = sC + wid * 1280;
#pragma unroll
            for (int mi = 0; mi < 2; mi++) {
#pragma unroll
                for (int jj = 0; jj < 4; jj++) {
                    int m0 = mi * 16 + grp, n0 = jj * 8 + tig * 2;
                    cw[m0 * 40 + n0]           = cf[mi][jj][0];
                    cw[m0 * 40 + n0 + 1]       = cf[mi][jj][1];
                    cw[(m0 + 8) * 40 + n0]     = cf[mi][jj][2];
                    cw[(m0 + 8) * 40 + n0 + 1] = cf[mi][jj][3];
                }
            }
        }
        __syncthreads();

        // reduce 8 K-slices -> sG[32][32]
        {
            int rm = tid >> 3, rb = (tid & 7) * 4;
            float4 a = *(float4*)(sC + rm * 40 + rb);
#pragma unroll
            for (int w2 = 1; w2 < 8; w2++) {
                float4 p = *(float4*)(sC + w2 * 1280 + rm * 40 + rb);
                a.x += p.x; a.y += p.y; a.z += p.z; a.w += p.w;
            }
            *(float4*)(sG + rm * 32 + rb) = a;
        }
        __syncthreads();

        // pointwise (thread (wid=unit, lane=batch))
        {
            float gi = sigmoidf_(sG[(0 * 8 + wid) * 32 + lane] + xv0);
            float gf = sigmoidf_(sG[(1 * 8 + wid) * 32 + lane] + xv1);
            float gg = tanhf   (sG[(2 * 8 + wid) * 32 + lane] + xv2);
            float go = sigmoidf_(sG[(3 * 8 + wid) * 32 + lane] + xv3);
            float cn = gf * cc + gi * gg;
            float hn = go * tanhf(cn);
            if (t < mylen) { cc = cn; hh = hn; }
            __nv_bfloat16 hi = __float2bfloat16(hh);
            sPub[0][lane][wid] = hi;
            sPub[1][lane][wid] = __float2bfloat16(hh - __bfloat162float(hi));
            sOut[lane][wid] = hh;
        }
        __syncthreads();

        // publish h (16B per (split,b) row) then release
        if (tid < 64) {
            int split = tid >> 5, b = tid & 31;
            __stcg((float4*)(g_hb + (size_t)((buf ^ 1) * 2 + dir) * 2 * 16384
                             + (size_t)split * 16384 + b * 512 + jbase),
                   *(float4*)&sPub[split][b][0]);
        }
        __threadfence();
        __syncthreads();
        if (tid == 0) ((volatile int*)g_flags)[blk] = s + 1;
        if (tid >= 64 && tid < 128) {
            int idx = tid - 64;
            int b = idx >> 1, half = idx & 1;
            float4 v;
            v.x = sOut[b][half * 4 + 0]; v.y = sOut[b][half * 4 + 1];
            v.z = sOut[b][half * 4 + 2]; v.w = sOut[b][half * 4 + 3];
            *(float4*)(out + ((size_t)(b * TT + t)) * 1024 + dir * HH + jbase + half * 4) = v;
        }
        if (tid < 64) {
            volatile int* f = (volatile int*)&g_flags[dir * 64 + tid];
            while (*f < s + 1) { }
        }
        __syncthreads();
    }
}

// ---------------------------------------------------------------------------
extern "C" void kernel_launch(void* const* d_in, const int* in_sizes, int n_in,
                              void* d_out, int out_size) {
    const float* x      = (const float*)d_in[0];
    const int*   lens   = (const int*)  d_in[1];
    const float* W_ih_f = (const float*)d_in[2];
    const float* W_hh_f = (const float*)d_in[3];
    const float* b_ih_f = (const float*)d_in[4];
    const float* b_hh_f = (const float*)d_in[5];
    const float* W_ih_b = (const float*)d_in[6];
    const float* W_hh_b = (const float*)d_in[7];
    const float* b_ih_b = (const float*)d_in[8];
    const float* b_hh_b = (const float*)d_in[9];
    float* out = (float*)d_out;

    cudaFuncSetAttribute(xg_mma,     cudaFuncAttributeMaxDynamicSharedMemorySize, 2 * XG_BUF);
    cudaFuncSetAttribute(rec_kernel, cudaFuncAttributeMaxDynamicSharedMemorySize, 131072);

    init_kernel<<<256, 256>>>();
    prep_w<<<(2 * G4 * DD + 255) / 256, 256>>>(W_ih_f, W_ih_b);
    prep_whh<<<(2 * G4 * HH + 255) / 256, 256>>>(W_hh_f, W_hh_b);
    prep_x<<<(BB * TT * DD + 255) / 256, 256>>>(x);
    xg_mma<<<dim3(256, 32), 256, 2 * XG_BUF>>>(b_ih_f, b_hh_f, b_ih_b, b_hh_b);
    rec_kernel<<<NBLK, 256, 131072>>>(lens, out);
}